// round 1
// baseline (speedup 1.0000x reference)
#include <cuda_runtime.h>
#include <cuda_bf16.h>

// Problem constants
#define BB 2
#define TT 2048
#define DD 1024
#define HH 4
#define KD 512
#define VD 1024
#define DK 128
#define DV 256
#define CHUNK 64
#define NC 32
#define MROWS (BB*TT)          // 4096
#define LOW_RANK 16
#define SCALE 0.08838834764831845f   // 1/sqrt(128)
#define INV_NORMALIZER 0.0625f       // 1/16

// ---------------- scratch (static device allocations) ----------------
__device__ float g_q[MROWS*KD];
__device__ float g_k[MROWS*KD];
__device__ float g_v[MROWS*VD];
__device__ float g_g[MROWS*VD];
__device__ float g_low[MROWS*LOW_RANK];
__device__ float g_G[MROWS*KD];
__device__ float g_S[NC*BB*HH*DK*DV];   // S_prev per chunk
__device__ float g_o[MROWS*VD];

// ---------------- generic fp32 SGEMM: C = A(MxK) @ B(KxN), row-major ----------------
// Requires M%128==0, N%128==0, K%8==0 (true for all uses here).
#define BM 128
#define BN 128
#define BKK 8
#define TM 8
#define TN 8
__global__ __launch_bounds__(256) void sgemm_kernel(const float* __restrict__ A,
                                                    const float* __restrict__ Bm,
                                                    float* __restrict__ C,
                                                    int M, int N, int K) {
    __shared__ float As[BKK][BM];
    __shared__ float Bs[BKK][BN];
    const int tid  = threadIdx.x;
    const int tcol = tid % 16;
    const int trow = tid / 16;

    A  += (size_t)blockIdx.y * BM * K;
    Bm += (size_t)blockIdx.x * BN;
    C  += (size_t)blockIdx.y * BM * N + (size_t)blockIdx.x * BN;

    const int arow = tid / 2;            // 128 rows
    const int acol = (tid % 2) * 4;      // 8 cols via float4
    const int brow = tid / 32;           // 8 rows
    const int bcol = (tid % 32) * 4;     // 128 cols via float4

    float acc[TM][TN];
#pragma unroll
    for (int i = 0; i < TM; i++)
#pragma unroll
        for (int j = 0; j < TN; j++) acc[i][j] = 0.f;

    for (int k0 = 0; k0 < K; k0 += BKK) {
        float4 a4 = *reinterpret_cast<const float4*>(&A[(size_t)arow * K + k0 + acol]);
        As[acol + 0][arow] = a4.x;
        As[acol + 1][arow] = a4.y;
        As[acol + 2][arow] = a4.z;
        As[acol + 3][arow] = a4.w;
        float4 b4 = *reinterpret_cast<const float4*>(&Bm[(size_t)(k0 + brow) * N + bcol]);
        *reinterpret_cast<float4*>(&Bs[brow][bcol]) = b4;
        __syncthreads();
#pragma unroll
        for (int kk = 0; kk < BKK; kk++) {
            float ra[TM], rb[TN];
#pragma unroll
            for (int i = 0; i < TM; i++) ra[i] = As[kk][trow * TM + i];
#pragma unroll
            for (int j = 0; j < TN; j++) rb[j] = Bs[kk][tcol * TN + j];
#pragma unroll
            for (int i = 0; i < TM; i++)
#pragma unroll
                for (int j = 0; j < TN; j++) acc[i][j] += ra[i] * rb[j];
        }
        __syncthreads();
    }
#pragma unroll
    for (int i = 0; i < TM; i++) {
#pragma unroll
        for (int j = 0; j < TN; j += 4) {
            float4 o4 = make_float4(acc[i][j], acc[i][j+1], acc[i][j+2], acc[i][j+3]);
            *reinterpret_cast<float4*>(&C[(size_t)(trow * TM + i) * N + tcol * TN + j]) = o4;
        }
    }
}

// ---------------- low-rank projection: g_low = x @ Wgk1  (4096x1024 @ 1024x16) ----------------
__global__ __launch_bounds__(256) void lowrank_kernel(const float* __restrict__ x,
                                                      const float* __restrict__ Wgk1) {
    int id = blockIdx.x * 256 + threadIdx.x;   // MROWS*16 threads
    int row = id >> 4;
    int r   = id & 15;
    const float* xr = x + (size_t)row * DD;
    float acc = 0.f;
#pragma unroll 4
    for (int k = 0; k < DD; k++) acc += xr[k] * Wgk1[k * LOW_RANK + r];
    g_low[row * LOW_RANK + r] = acc;
}

// ---------------- gate: gk = log_sigmoid(low @ Wgk2 + b)/16, cumsum within chunk ----------------
__global__ __launch_bounds__(256) void gkcum_kernel(const float* __restrict__ Wgk2,
                                                    const float* __restrict__ bgk2) {
    int id = blockIdx.x * 256 + threadIdx.x;   // BB*NC*KD = 32768 threads
    int col = id % KD;
    int bn  = id / KD;
    int b   = bn / NC;
    int n   = bn % NC;
    float w[LOW_RANK];
#pragma unroll
    for (int r = 0; r < LOW_RANK; r++) w[r] = Wgk2[r * KD + col];
    float bias = bgk2[col];
    float cum = 0.f;
    int row0 = b * TT + n * CHUNK;
    for (int c = 0; c < CHUNK; c++) {
        const float* lr = &g_low[(row0 + c) * LOW_RANK];
        float z = bias;
#pragma unroll
        for (int r = 0; r < LOW_RANK; r++) z += lr[r] * w[r];
        // stable log_sigmoid
        float ls = fminf(z, 0.f) - log1pf(expf(-fabsf(z)));
        cum += ls * INV_NORMALIZER;
        g_G[(size_t)(row0 + c) * KD + col] = cum;
    }
}

// ---------------- sequential chunk scan; stores S_prev for every chunk ----------------
// grid: (DV/32, DK/32, BB*HH), block: (32,32). One thread owns one S element.
__global__ __launch_bounds__(1024) void scan_kernel() {
    const int j0 = blockIdx.x * 32;
    const int i0 = blockIdx.y * 32;
    const int bh = blockIdx.z;
    const int b  = bh >> 2;
    const int h  = bh & 3;
    const int tx = threadIdx.x, ty = threadIdx.y;

    __shared__ float kb[CHUNK][33];
    __shared__ float vv[CHUNK][33];
    __shared__ float gl[32];

    float s = 0.f;
    for (int n = 0; n < NC; n++) {
        const int row0 = b * TT + n * CHUNK;
        if (ty == 0)
            gl[tx] = g_G[(size_t)(row0 + CHUNK - 1) * KD + h * DK + i0 + tx];
        __syncthreads();
#pragma unroll
        for (int cc = 0; cc < 2; cc++) {
            int c = ty + cc * 32;
            size_t gidx = (size_t)(row0 + c) * KD + h * DK + i0 + tx;
            kb[c][tx] = g_k[gidx] * expf(gl[tx] - g_G[gidx]);
            vv[c][tx] = g_v[(size_t)(row0 + c) * VD + h * DV + j0 + tx];
        }
        __syncthreads();
        // store S_prev (state BEFORE this chunk's update)
        g_S[(size_t)((n * (BB*HH) + bh) * DK + i0 + ty) * DV + j0 + tx] = s;
        float contrib = 0.f;
#pragma unroll
        for (int c = 0; c < CHUNK; c++) contrib += kb[c][ty] * vv[c][tx];
        s = expf(gl[ty]) * s + contrib;
        __syncthreads();
    }
}

// ---------------- intra-chunk attention + inter (qg @ S_prev) ----------------
// grid: (NC, BB*HH), 256 threads, dynamic smem: qg[64][129], kg[64][129], A[64][65]
__global__ __launch_bounds__(256) void intra_kernel() {
    extern __shared__ float sm[];
    float (*qg)[129] = (float(*)[129])sm;
    float (*kg)[129] = (float(*)[129])(sm + 64 * 129);
    float (*As)[65]  = (float(*)[65]) (sm + 2 * 64 * 129);

    const int n  = blockIdx.x;
    const int bh = blockIdx.y;
    const int b  = bh >> 2;
    const int h  = bh & 3;
    const int tid = threadIdx.x;
    const int row0 = b * TT + n * CHUNK;

    // phase 1: qg = q*exp(G)*scale, kg = k*exp(-G)
    for (int idx = tid; idx < CHUNK * DK; idx += 256) {
        int c  = idx >> 7;
        int kk = idx & 127;
        size_t gi = (size_t)(row0 + c) * KD + h * DK + kk;
        float Gv = g_G[gi];
        qg[c][kk] = g_q[gi] * expf(Gv) * SCALE;
        kg[c][kk] = g_k[gi] * expf(-Gv);
    }
    __syncthreads();

    // phase 2: A[i][j] = sum_k qg[i][k]*kg[j][k], zero for j>i (mask baked in)
    for (int p = 0; p < 16; p++) {
        int idx = p * 256 + tid;
        int i = idx >> 6;
        int j = idx & 63;
        float a = 0.f;
        if (j <= i) {
#pragma unroll 8
            for (int kk = 0; kk < DK; kk++) a += qg[i][kk] * kg[j][kk];
        }
        As[i][j] = a;
    }
    __syncthreads();

    // phase 3: per-output-column accumulation, jv = tid in [0,256)
    const int jv = tid;
    float acc[CHUNK];
#pragma unroll
    for (int c = 0; c < CHUNK; c++) acc[c] = 0.f;

    const float* Sp = &g_S[(size_t)((n * (BB*HH) + bh) * DK) * DV + jv];
    for (int kk = 0; kk < DK; kk++) {
        float sv = __ldg(&Sp[(size_t)kk * DV]);
#pragma unroll
        for (int c = 0; c < CHUNK; c++) acc[c] += qg[c][kk] * sv;
    }
    for (int j = 0; j < CHUNK; j++) {
        float vvv = g_v[(size_t)(row0 + j) * VD + h * DV + jv];
#pragma unroll
        for (int c = 0; c < CHUNK; c++) acc[c] += As[c][j] * vvv;  // As==0 above diag
    }
#pragma unroll
    for (int c = 0; c < CHUNK; c++)
        g_o[(size_t)(row0 + c) * VD + h * DV + jv] = acc[c];
}

// ---------------- group RMSNorm + SiLU gating (one warp per (b,t,h) row) ----------------
__global__ __launch_bounds__(256) void normgate_kernel(const float* __restrict__ gnorm_w) {
    int warp = (blockIdx.x * 256 + threadIdx.x) >> 5;   // over MROWS*HH = 16384
    int lane = threadIdx.x & 31;
    size_t base = (size_t)(warp >> 2) * VD + (size_t)(warp & 3) * DV;
    float v[8];
    float ss = 0.f;
#pragma unroll
    for (int l = 0; l < 8; l++) {
        v[l] = g_o[base + lane + l * 32];
        ss += v[l] * v[l];
    }
#pragma unroll
    for (int o = 16; o; o >>= 1) ss += __shfl_xor_sync(0xffffffffu, ss, o);
    float r = rsqrtf(ss * (1.f / 256.f) + 1e-6f);
#pragma unroll
    for (int l = 0; l < 8; l++) {
        int j = lane + l * 32;
        float gvv = g_g[base + j];
        float sig = 1.f / (1.f + expf(-gvv));
        g_o[base + j] = v[l] * r * gnorm_w[j] * (gvv * sig);
    }
}

// ---------------- launch ----------------
extern "C" void kernel_launch(void* const* d_in, const int* in_sizes, int n_in,
                              void* d_out, int out_size) {
    const float* x      = (const float*)d_in[0];
    const float* Wq     = (const float*)d_in[1];
    const float* Wk     = (const float*)d_in[2];
    const float* Wv     = (const float*)d_in[3];
    const float* Wg     = (const float*)d_in[4];
    const float* Wgk1   = (const float*)d_in[5];
    const float* Wgk2   = (const float*)d_in[6];
    const float* bgk2   = (const float*)d_in[7];
    const float* gnormw = (const float*)d_in[8];
    const float* Wo     = (const float*)d_in[9];
    float* out = (float*)d_out;

    float *q, *k, *v, *g, *o;
    cudaGetSymbolAddress((void**)&q, g_q);
    cudaGetSymbolAddress((void**)&k, g_k);
    cudaGetSymbolAddress((void**)&v, g_v);
    cudaGetSymbolAddress((void**)&g, g_g);
    cudaGetSymbolAddress((void**)&o, g_o);

    const int smem_intra = (2 * 64 * 129 + 64 * 65) * (int)sizeof(float);  // 82688 B
    cudaFuncSetAttribute(intra_kernel, cudaFuncAttributeMaxDynamicSharedMemorySize, smem_intra);

    dim3 blk(256);
    // projections
    sgemm_kernel<<<dim3(KD / BN, MROWS / BM), blk>>>(x, Wq, q, MROWS, KD, DD);
    sgemm_kernel<<<dim3(KD / BN, MROWS / BM), blk>>>(x, Wk, k, MROWS, KD, DD);
    sgemm_kernel<<<dim3(VD / BN, MROWS / BM), blk>>>(x, Wv, v, MROWS, VD, DD);
    sgemm_kernel<<<dim3(VD / BN, MROWS / BM), blk>>>(x, Wg, g, MROWS, VD, DD);
    // gates
    lowrank_kernel<<<MROWS * LOW_RANK / 256, blk>>>(x, Wgk1);
    gkcum_kernel<<<BB * NC * KD / 256, blk>>>(Wgk2, bgk2);
    // chunked scan
    scan_kernel<<<dim3(DV / 32, DK / 32, BB * HH), dim3(32, 32)>>>();
    // intra + inter
    intra_kernel<<<dim3(NC, BB * HH), blk, smem_intra>>>();
    // norm + gate
    normgate_kernel<<<MROWS * HH / 8, blk>>>(gnormw);
    // output projection
    sgemm_kernel<<<dim3(DD / BN, MROWS / BM), blk>>>(o, Wo, out, MROWS, DD, DD);
}

// round 3
// speedup vs baseline: 1.8003x; 1.8003x over previous
#include <cuda_runtime.h>
#include <cuda_bf16.h>

// Problem constants
#define BB 2
#define TT 2048
#define DD 1024
#define HH 4
#define KD 512
#define VD 1024
#define DK 128
#define DV 256
#define CHUNK 64
#define NC 32
#define MROWS (BB*TT)          // 4096
#define LOW_RANK 16
#define SCALE 0.08838834764831845f   // 1/sqrt(128)
#define INV_NORMALIZER 0.0625f       // 1/16

// ---------------- scratch (static device allocations) ----------------
__device__ float g_q[MROWS*KD];
__device__ float g_k[MROWS*KD];
__device__ float g_v[MROWS*VD];
__device__ float g_g[MROWS*VD];
__device__ float g_low[MROWS*LOW_RANK];
__device__ float g_G[MROWS*KD];
__device__ float g_S[NC*BB*HH*DK*DV];   // S_prev per chunk
__device__ float g_o[MROWS*VD];

// ---------------- tf32 tensor-core GEMM: C = A(MxK) @ B(KxN), row-major ----------------
// Block tile 128x128, k-tile 32, 256 threads (8 warps, warp tile 32x64).
// Requires M%128==0, N%128==0, K%32==0.

__device__ __forceinline__ unsigned f2tf(float f) {
    unsigned u;
    asm("cvt.rna.tf32.f32 %0, %1;" : "=r"(u) : "f"(f));
    return u;
}

#define AS_STRIDE 36
#define BS_STRIDE 136
#define AS_BUF (128*AS_STRIDE)   // 4608 floats
#define BS_BUF (32*BS_STRIDE)    // 4352 floats
#define SMEM_GEMM_BYTES ((2*AS_BUF + 2*BS_BUF)*4)   // 71680

__global__ __launch_bounds__(256, 1) void tf32gemm_kernel(const float* __restrict__ A,
                                                          const float* __restrict__ Bm,
                                                          float* __restrict__ C,
                                                          int M, int N, int K) {
    extern __shared__ float sm[];
    float* As = sm;                 // [2][128][36]
    float* Bs = sm + 2 * AS_BUF;    // [2][32][136]

    const int tid  = threadIdx.x;
    const int wid  = tid >> 5;
    const int lane = tid & 31;
    const int g    = lane >> 2;     // 0..7
    const int tig  = lane & 3;      // 0..3
    const int wm   = wid >> 1;      // 0..3
    const int wn   = wid & 1;       // 0..1
    const int row0 = wm * 32;
    const int col0 = wn * 64;

    A  += (size_t)blockIdx.y * 128 * K;
    Bm += (size_t)blockIdx.x * 128;
    C  += (size_t)blockIdx.y * 128 * N + (size_t)blockIdx.x * 128;

    // staging assignment
    const int ar  = tid >> 1;            // A row 0..127
    const int ac0 = (tid & 1) * 16;      // A col base (floats)
    const int br  = tid >> 3;            // B k-row 0..31
    const int bc0 = (tid & 7) * 4;       // B col base (floats), +32 per i

    float4 aReg[4], bReg[4];

    float c[2][8][4];
#pragma unroll
    for (int mt = 0; mt < 2; mt++)
#pragma unroll
        for (int nt = 0; nt < 8; nt++)
#pragma unroll
            for (int i = 0; i < 4; i++) c[mt][nt][i] = 0.f;

    const int ntiles = K / 32;

    // prefetch tile 0
#pragma unroll
    for (int i = 0; i < 4; i++)
        aReg[i] = *reinterpret_cast<const float4*>(&A[(size_t)ar * K + ac0 + i * 4]);
#pragma unroll
    for (int i = 0; i < 4; i++)
        bReg[i] = *reinterpret_cast<const float4*>(&Bm[(size_t)br * N + bc0 + i * 32]);

    // store tile 0 into buffer 0 (with tf32 rounding)
#pragma unroll
    for (int i = 0; i < 4; i++) {
        float4 t = aReg[i];
        float4 o = make_float4(__uint_as_float(f2tf(t.x)), __uint_as_float(f2tf(t.y)),
                               __uint_as_float(f2tf(t.z)), __uint_as_float(f2tf(t.w)));
        *reinterpret_cast<float4*>(&As[ar * AS_STRIDE + ac0 + i * 4]) = o;
    }
#pragma unroll
    for (int i = 0; i < 4; i++) {
        float4 t = bReg[i];
        float4 o = make_float4(__uint_as_float(f2tf(t.x)), __uint_as_float(f2tf(t.y)),
                               __uint_as_float(f2tf(t.z)), __uint_as_float(f2tf(t.w)));
        *reinterpret_cast<float4*>(&Bs[br * BS_STRIDE + bc0 + i * 32]) = o;
    }
    __syncthreads();

    for (int t = 0; t < ntiles; t++) {
        // issue next tile's global loads early
        if (t + 1 < ntiles) {
            const float* Ap = A + (t + 1) * 32;
            const float* Bp = Bm + (size_t)(t + 1) * 32 * N;
#pragma unroll
            for (int i = 0; i < 4; i++)
                aReg[i] = *reinterpret_cast<const float4*>(&Ap[(size_t)ar * K + ac0 + i * 4]);
#pragma unroll
            for (int i = 0; i < 4; i++)
                bReg[i] = *reinterpret_cast<const float4*>(&Bp[(size_t)br * N + bc0 + i * 32]);
        }

        const float* Ab = As + (t & 1) * AS_BUF;
        const float* Bb = Bs + (t & 1) * BS_BUF;

#pragma unroll
        for (int ks = 0; ks < 4; ks++) {
            unsigned a[2][4];
#pragma unroll
            for (int mt = 0; mt < 2; mt++) {
                int row = row0 + mt * 16 + g;
                a[mt][0] = __float_as_uint(Ab[row * AS_STRIDE + ks * 8 + tig]);
                a[mt][1] = __float_as_uint(Ab[(row + 8) * AS_STRIDE + ks * 8 + tig]);
                a[mt][2] = __float_as_uint(Ab[row * AS_STRIDE + ks * 8 + tig + 4]);
                a[mt][3] = __float_as_uint(Ab[(row + 8) * AS_STRIDE + ks * 8 + tig + 4]);
            }
#pragma unroll
            for (int nt = 0; nt < 8; nt++) {
                int col = col0 + nt * 8 + g;
                unsigned b0 = __float_as_uint(Bb[(ks * 8 + tig) * BS_STRIDE + col]);
                unsigned b1 = __float_as_uint(Bb[(ks * 8 + tig + 4) * BS_STRIDE + col]);
#pragma unroll
                for (int mt = 0; mt < 2; mt++) {
                    asm volatile(
                        "mma.sync.aligned.m16n8k8.row.col.f32.tf32.tf32.f32 "
                        "{%0,%1,%2,%3}, {%4,%5,%6,%7}, {%8,%9}, {%0,%1,%2,%3};"
                        : "+f"(c[mt][nt][0]), "+f"(c[mt][nt][1]),
                          "+f"(c[mt][nt][2]), "+f"(c[mt][nt][3])
                        : "r"(a[mt][0]), "r"(a[mt][1]), "r"(a[mt][2]), "r"(a[mt][3]),
                          "r"(b0), "r"(b1));
                }
            }
        }
        __syncthreads();

        if (t + 1 < ntiles) {
            float* Ab2 = As + ((t + 1) & 1) * AS_BUF;
            float* Bb2 = Bs + ((t + 1) & 1) * BS_BUF;
#pragma unroll
            for (int i = 0; i < 4; i++) {
                float4 tt = aReg[i];
                float4 o = make_float4(__uint_as_float(f2tf(tt.x)), __uint_as_float(f2tf(tt.y)),
                                       __uint_as_float(f2tf(tt.z)), __uint_as_float(f2tf(tt.w)));
                *reinterpret_cast<float4*>(&Ab2[ar * AS_STRIDE + ac0 + i * 4]) = o;
            }
#pragma unroll
            for (int i = 0; i < 4; i++) {
                float4 tt = bReg[i];
                float4 o = make_float4(__uint_as_float(f2tf(tt.x)), __uint_as_float(f2tf(tt.y)),
                                       __uint_as_float(f2tf(tt.z)), __uint_as_float(f2tf(tt.w)));
                *reinterpret_cast<float4*>(&Bb2[br * BS_STRIDE + bc0 + i * 32]) = o;
            }
            __syncthreads();
        }
    }

    // epilogue
#pragma unroll
    for (int mt = 0; mt < 2; mt++) {
#pragma unroll
        for (int nt = 0; nt < 8; nt++) {
            int row = row0 + mt * 16 + g;
            int col = col0 + nt * 8 + 2 * tig;
            *reinterpret_cast<float2*>(&C[(size_t)row * N + col]) =
                make_float2(c[mt][nt][0], c[mt][nt][1]);
            *reinterpret_cast<float2*>(&C[(size_t)(row + 8) * N + col]) =
                make_float2(c[mt][nt][2], c[mt][nt][3]);
        }
    }
}

// ---------------- low-rank projection: g_low = x @ Wgk1  (4096x1024 @ 1024x16) ----------------
__global__ __launch_bounds__(256) void lowrank_kernel(const float* __restrict__ x,
                                                      const float* __restrict__ Wgk1) {
    int id = blockIdx.x * 256 + threadIdx.x;   // MROWS*16 threads
    int row = id >> 4;
    int r   = id & 15;
    const float* xr = x + (size_t)row * DD;
    float acc = 0.f;
#pragma unroll 4
    for (int k = 0; k < DD; k++) acc += xr[k] * Wgk1[k * LOW_RANK + r];
    g_low[row * LOW_RANK + r] = acc;
}

// ---------------- gate: gk = log_sigmoid(low @ Wgk2 + b)/16, cumsum within chunk ----------------
__global__ __launch_bounds__(256) void gkcum_kernel(const float* __restrict__ Wgk2,
                                                    const float* __restrict__ bgk2) {
    int id = blockIdx.x * 256 + threadIdx.x;   // BB*NC*KD = 32768 threads
    int col = id % KD;
    int bn  = id / KD;
    int b   = bn / NC;
    int n   = bn % NC;
    float w[LOW_RANK];
#pragma unroll
    for (int r = 0; r < LOW_RANK; r++) w[r] = Wgk2[r * KD + col];
    float bias = bgk2[col];
    float cum = 0.f;
    int row0 = b * TT + n * CHUNK;
    for (int c = 0; c < CHUNK; c++) {
        const float* lr = &g_low[(row0 + c) * LOW_RANK];
        float z = bias;
#pragma unroll
        for (int r = 0; r < LOW_RANK; r++) z += lr[r] * w[r];
        // stable log_sigmoid
        float ls = fminf(z, 0.f) - log1pf(expf(-fabsf(z)));
        cum += ls * INV_NORMALIZER;
        g_G[(size_t)(row0 + c) * KD + col] = cum;
    }
}

// ---------------- sequential chunk scan; stores S_prev for every chunk ----------------
// grid: (DV/32, DK/32, BB*HH), block: (32,32). One thread owns one S element.
__global__ __launch_bounds__(1024) void scan_kernel() {
    const int j0 = blockIdx.x * 32;
    const int i0 = blockIdx.y * 32;
    const int bh = blockIdx.z;
    const int b  = bh >> 2;
    const int h  = bh & 3;
    const int tx = threadIdx.x, ty = threadIdx.y;

    __shared__ float kb[CHUNK][33];
    __shared__ float vv[CHUNK][33];
    __shared__ float gl[32];

    float s = 0.f;
    for (int n = 0; n < NC; n++) {
        const int row0 = b * TT + n * CHUNK;
        if (ty == 0)
            gl[tx] = g_G[(size_t)(row0 + CHUNK - 1) * KD + h * DK + i0 + tx];
        __syncthreads();
#pragma unroll
        for (int cc = 0; cc < 2; cc++) {
            int c = ty + cc * 32;
            size_t gidx = (size_t)(row0 + c) * KD + h * DK + i0 + tx;
            kb[c][tx] = g_k[gidx] * expf(gl[tx] - g_G[gidx]);
            vv[c][tx] = g_v[(size_t)(row0 + c) * VD + h * DV + j0 + tx];
        }
        __syncthreads();
        // store S_prev (state BEFORE this chunk's update)
        g_S[(size_t)((n * (BB*HH) + bh) * DK + i0 + ty) * DV + j0 + tx] = s;
        float contrib = 0.f;
#pragma unroll
        for (int c = 0; c < CHUNK; c++) contrib += kb[c][ty] * vv[c][tx];
        s = expf(gl[ty]) * s + contrib;
        __syncthreads();
    }
}

// ---------------- intra-chunk attention + inter (qg @ S_prev) ----------------
// grid: (NC, BB*HH), 256 threads, dynamic smem: qg[64][129], kg[64][129], A[64][65]
__global__ __launch_bounds__(256) void intra_kernel() {
    extern __shared__ float sm[];
    float (*qg)[129] = (float(*)[129])sm;
    float (*kg)[129] = (float(*)[129])(sm + 64 * 129);
    float (*As)[65]  = (float(*)[65]) (sm + 2 * 64 * 129);

    const int n  = blockIdx.x;
    const int bh = blockIdx.y;
    const int b  = bh >> 2;
    const int h  = bh & 3;
    const int tid = threadIdx.x;
    const int row0 = b * TT + n * CHUNK;

    // phase 1: qg = q*exp(G)*scale, kg = k*exp(-G)
    for (int idx = tid; idx < CHUNK * DK; idx += 256) {
        int c  = idx >> 7;
        int kk = idx & 127;
        size_t gi = (size_t)(row0 + c) * KD + h * DK + kk;
        float Gv = g_G[gi];
        qg[c][kk] = g_q[gi] * expf(Gv) * SCALE;
        kg[c][kk] = g_k[gi] * expf(-Gv);
    }
    __syncthreads();

    // phase 2: A[i][j] = sum_k qg[i][k]*kg[j][k], zero for j>i (mask baked in)
    for (int p = 0; p < 16; p++) {
        int idx = p * 256 + tid;
        int i = idx >> 6;
        int j = idx & 63;
        float a = 0.f;
        if (j <= i) {
#pragma unroll 8
            for (int kk = 0; kk < DK; kk++) a += qg[i][kk] * kg[j][kk];
        }
        As[i][j] = a;
    }
    __syncthreads();

    // phase 3: per-output-column accumulation, jv = tid in [0,256)
    const int jv = tid;
    float acc[CHUNK];
#pragma unroll
    for (int c = 0; c < CHUNK; c++) acc[c] = 0.f;

    const float* Sp = &g_S[(size_t)((n * (BB*HH) + bh) * DK) * DV + jv];
    for (int kk = 0; kk < DK; kk++) {
        float sv = __ldg(&Sp[(size_t)kk * DV]);
#pragma unroll
        for (int c = 0; c < CHUNK; c++) acc[c] += qg[c][kk] * sv;
    }
    for (int j = 0; j < CHUNK; j++) {
        float vvv = g_v[(size_t)(row0 + j) * VD + h * DV + jv];
#pragma unroll
        for (int c = 0; c < CHUNK; c++) acc[c] += As[c][j] * vvv;  // As==0 above diag
    }
#pragma unroll
    for (int c = 0; c < CHUNK; c++)
        g_o[(size_t)(row0 + c) * VD + h * DV + jv] = acc[c];
}

// ---------------- group RMSNorm + SiLU gating (one warp per (b,t,h) row) ----------------
__global__ __launch_bounds__(256) void normgate_kernel(const float* __restrict__ gnorm_w) {
    int warp = (blockIdx.x * 256 + threadIdx.x) >> 5;   // over MROWS*HH = 16384
    int lane = threadIdx.x & 31;
    size_t base = (size_t)(warp >> 2) * VD + (size_t)(warp & 3) * DV;
    float v[8];
    float ss = 0.f;
#pragma unroll
    for (int l = 0; l < 8; l++) {
        v[l] = g_o[base + lane + l * 32];
        ss += v[l] * v[l];
    }
#pragma unroll
    for (int o = 16; o; o >>= 1) ss += __shfl_xor_sync(0xffffffffu, ss, o);
    float r = rsqrtf(ss * (1.f / 256.f) + 1e-6f);
#pragma unroll
    for (int l = 0; l < 8; l++) {
        int j = lane + l * 32;
        float gvv = g_g[base + j];
        float sig = 1.f / (1.f + expf(-gvv));
        g_o[base + j] = v[l] * r * gnorm_w[j] * (gvv * sig);
    }
}

// ---------------- launch ----------------
extern "C" void kernel_launch(void* const* d_in, const int* in_sizes, int n_in,
                              void* d_out, int out_size) {
    const float* x      = (const float*)d_in[0];
    const float* Wq     = (const float*)d_in[1];
    const float* Wk     = (const float*)d_in[2];
    const float* Wv     = (const float*)d_in[3];
    const float* Wg     = (const float*)d_in[4];
    const float* Wgk1   = (const float*)d_in[5];
    const float* Wgk2   = (const float*)d_in[6];
    const float* bgk2   = (const float*)d_in[7];
    const float* gnormw = (const float*)d_in[8];
    const float* Wo     = (const float*)d_in[9];
    float* out = (float*)d_out;

    float *q, *k, *v, *g, *o;
    cudaGetSymbolAddress((void**)&q, g_q);
    cudaGetSymbolAddress((void**)&k, g_k);
    cudaGetSymbolAddress((void**)&v, g_v);
    cudaGetSymbolAddress((void**)&g, g_g);
    cudaGetSymbolAddress((void**)&o, g_o);

    const int smem_intra = (2 * 64 * 129 + 64 * 65) * (int)sizeof(float);  // 82688 B
    cudaFuncSetAttribute(intra_kernel, cudaFuncAttributeMaxDynamicSharedMemorySize, smem_intra);
    cudaFuncSetAttribute(tf32gemm_kernel, cudaFuncAttributeMaxDynamicSharedMemorySize, SMEM_GEMM_BYTES);

    dim3 blk(256);
    // projections (tensor cores, tf32)
    tf32gemm_kernel<<<dim3(KD / 128, MROWS / 128), blk, SMEM_GEMM_BYTES>>>(x, Wq, q, MROWS, KD, DD);
    tf32gemm_kernel<<<dim3(KD / 128, MROWS / 128), blk, SMEM_GEMM_BYTES>>>(x, Wk, k, MROWS, KD, DD);
    tf32gemm_kernel<<<dim3(VD / 128, MROWS / 128), blk, SMEM_GEMM_BYTES>>>(x, Wv, v, MROWS, VD, DD);
    tf32gemm_kernel<<<dim3(VD / 128, MROWS / 128), blk, SMEM_GEMM_BYTES>>>(x, Wg, g, MROWS, VD, DD);
    // gates
    lowrank_kernel<<<MROWS * LOW_RANK / 256, blk>>>(x, Wgk1);
    gkcum_kernel<<<BB * NC * KD / 256, blk>>>(Wgk2, bgk2);
    // chunked scan
    scan_kernel<<<dim3(DV / 32, DK / 32, BB * HH), dim3(32, 32)>>>();
    // intra + inter
    intra_kernel<<<dim3(NC, BB * HH), blk, smem_intra>>>();
    // norm + gate
    normgate_kernel<<<MROWS * HH / 8, blk>>>(gnormw);
    // output projection (tensor cores, tf32)
    tf32gemm_kernel<<<dim3(DD / 128, MROWS / 128), blk, SMEM_GEMM_BYTES>>>(o, Wo, out, MROWS, DD, DD);
}